// round 12
// baseline (speedup 1.0000x reference)
#include <cuda_runtime.h>
#include <cstdint>
#include <cmath>

// ============================================================================
// W8A8B32O32 Linear — hybrid tensor+dp4a, issue-balanced 80/48 split.
// out[8192,4096](f32) = X[8192,4096](s8) @ W[4096,4096](s8)^T + bias(s32)
//
// R11 diagnosis: issue-slot bound; dp4a warps consume ~5200 issues/SMSP/stage
// vs mma's 420, pinning tensor at 64%. This build shifts columns to the
// issue-cheap tensor pipe (80 mma / 48 dp4a), stores the dp4a-B region
// UNswizzled (no XOR ALU on b-loads), and uses immediate-offset LDS
// addressing to fit 80 mma accumulators without spilling.
// 2 CTAs/SM (3-stage, 96KB smem, 256 threads, <=128 regs).
// ============================================================================

#define M_TOTAL   8192
#define N_TOTAL   4096
#define K_TOTAL   4096

#define THREADS   256

#define TILE_M    128
#define TILE_N    128
#define TILE_K    128
#define K_ITERS   (K_TOTAL / TILE_K)   // 32
#define STAGES    3

#define N_MMA     80                   // cols 0-79  (4 warps, 10 n-tiles each)
#define N_DP      48                   // cols 80-127 (4 warps, 8x6 per thread)
#define NT_MMA    (N_MMA / 8)          // 10

#define A_BYTES      (TILE_M * TILE_K)            // 16384
#define B_BYTES      (TILE_N * TILE_K)            // 16384
#define B_DP_OFF     (A_BYTES + N_MMA * 128)      // dp4a-B region (linear)
#define STAGE_BYTES  (A_BYTES + B_BYTES)          // 32768
#define SMEM_BYTES   (STAGES * STAGE_BYTES)       // 98304 -> 2 CTAs/SM

// __device__ scratch (allocation-free rule)
__device__ int8_t g_x8[(size_t)M_TOTAL * K_TOTAL];
__device__ int8_t g_w8[(size_t)N_TOTAL * K_TOTAL];
__device__ int    g_bias[N_TOTAL];

// ---------------------------------------------------------------------------
// Stage 1: encoding detection + pack (proven R7-R11)
// ---------------------------------------------------------------------------
__device__ __forceinline__ int bf16_half_ok(uint32_t h, float rng) {
    if (h == 0) return -1;
    float f = __uint_as_float(h << 16);
    return (f == truncf(f) && fabsf(f) <= rng && f != 0.0f) ? 1 : 0;
}

__device__ __forceinline__ int detect_mode(const uint32_t* in32, int tid, int* cnt, float rng) {
    if (tid < 3) cnt[tid] = 0;
    __syncthreads();
    if (tid < 64) {
        const uint32_t w = in32[tid];
        const int   wi = (int)w;
        const float wf = __uint_as_float(w);
        if (wi != 0 && wi > (int)-rng && wi < (int)rng) atomicAdd(&cnt[0], 1);
        if (wf != 0.0f && wf == truncf(wf) && fabsf(wf) <= rng) atomicAdd(&cnt[1], 1);
        const int lo = bf16_half_ok(w & 0xFFFFu, rng);
        const int hi = bf16_half_ok(w >> 16, rng);
        if (lo != 0 && hi != 0 && (lo == 1 || hi == 1)) atomicAdd(&cnt[2], 1);
    }
    __syncthreads();
    if (cnt[0] >= 48) return 1;
    if (cnt[1] >= 48) return 2;
    if (cnt[2] >= 48) return 3;
    return 0;
}

__global__ void pack_s8_kernel(const uint8_t* __restrict__ in, int n_words, int which) {
    __shared__ int cnt[3];
    const int tid = threadIdx.x;
    const uint32_t* in32 = (const uint32_t*)in;
    const int mode = detect_mode(in32, tid, cnt, 128.0f);

    uint8_t* out = which ? (uint8_t*)g_w8 : (uint8_t*)g_x8;
    const int o = blockIdx.x * blockDim.x + tid;
    if (o >= n_words) return;

    uint32_t r;
    if (mode == 0) {
        r = in32[o];
    } else if (mode == 1) {
        const int4 v = ((const int4*)in)[o];
        r = (uint32_t)(v.x & 0xFF) | ((uint32_t)(v.y & 0xFF) << 8) |
            ((uint32_t)(v.z & 0xFF) << 16) | ((uint32_t)(v.w & 0xFF) << 24);
    } else if (mode == 2) {
        const float4 v = ((const float4*)in)[o];
        const int e0 = (int)v.x, e1 = (int)v.y, e2 = (int)v.z, e3 = (int)v.w;
        r = (uint32_t)(e0 & 0xFF) | ((uint32_t)(e1 & 0xFF) << 8) |
            ((uint32_t)(e2 & 0xFF) << 16) | ((uint32_t)(e3 & 0xFF) << 24);
    } else {
        const uint32_t w0 = in32[2 * o], w1 = in32[2 * o + 1];
        const int e0 = (int)__uint_as_float((w0 & 0xFFFFu) << 16);
        const int e1 = (int)__uint_as_float((w0 >> 16) << 16);
        const int e2 = (int)__uint_as_float((w1 & 0xFFFFu) << 16);
        const int e3 = (int)__uint_as_float((w1 >> 16) << 16);
        r = (uint32_t)(e0 & 0xFF) | ((uint32_t)(e1 & 0xFF) << 8) |
            ((uint32_t)(e2 & 0xFF) << 16) | ((uint32_t)(e3 & 0xFF) << 24);
    }
    ((uint32_t*)out)[o] = r;
}

__global__ void pack_bias_kernel(const uint8_t* __restrict__ in) {
    __shared__ int cnt[3];
    const int tid = threadIdx.x;
    const uint32_t* in32 = (const uint32_t*)in;
    const int mode = detect_mode(in32, tid, cnt, 100000.0f);

    const int o = blockIdx.x * blockDim.x + tid;
    if (o >= N_TOTAL) return;

    int v;
    if (mode == 2)      v = (int)__uint_as_float(in32[o]);
    else if (mode == 3) {
        const uint32_t h = (in32[o >> 1] >> ((o & 1) * 16)) & 0xFFFFu;
        v = (int)__uint_as_float(h << 16);
    } else              v = (int)in32[o];
    g_bias[o] = v;
}

// ---------------------------------------------------------------------------
// helpers
// ---------------------------------------------------------------------------
__device__ __forceinline__ uint32_t smem_u32(const void* p) {
    uint32_t a;
    asm("{ .reg .u64 t; cvta.to.shared.u64 t, %1; cvt.u32.u64 %0, t; }" : "=r"(a) : "l"(p));
    return a;
}
__device__ __forceinline__ void cp_async16(uint32_t dst, const void* src) {
    asm volatile("cp.async.cg.shared.global [%0], [%1], 16;" :: "r"(dst), "l"(src) : "memory");
}
__device__ __forceinline__ uint32_t lds32(uint32_t addr) {
    uint32_t v;
    asm volatile("ld.shared.b32 %0, [%1];" : "=r"(v) : "r"(addr));
    return v;
}
__device__ __forceinline__ void lds64(uint32_t& v0, uint32_t& v1, uint32_t addr) {
    asm volatile("ld.shared.v2.u32 {%0,%1}, [%2];" : "=r"(v0), "=r"(v1) : "r"(addr));
}
__device__ __forceinline__ void mma_s8(int* c, const uint32_t* a, const uint32_t* b) {
    asm volatile(
        "mma.sync.aligned.m16n8k32.row.col.s32.s8.s8.s32 "
        "{%0,%1,%2,%3}, {%4,%5,%6,%7}, {%8,%9}, {%0,%1,%2,%3};"
        : "+r"(c[0]), "+r"(c[1]), "+r"(c[2]), "+r"(c[3])
        : "r"(a[0]), "r"(a[1]), "r"(a[2]), "r"(a[3]), "r"(b[0]), "r"(b[1]));
}
__device__ __forceinline__ int dp4a_s(uint32_t a, uint32_t b, int c) {
    int r;
    asm("dp4a.s32.s32 %0, %1, %2, %3;" : "=r"(r) : "r"(a), "r"(b), "r"(c));
    return r;
}

// ---------------------------------------------------------------------------
// Stage 2: hybrid GEMM, 80/48 split, 2 CTAs/SM
// ---------------------------------------------------------------------------
__global__ void __launch_bounds__(THREADS, 2)
w8a8_hybrid_kernel(float* __restrict__ out) {
    extern __shared__ char smem[];
    const uint32_t smem_base = smem_u32(smem);
    const int tid = threadIdx.x;
    const int lane = tid & 31;
    const int wid = tid >> 5;
    const bool is_mma = (wid < 4);

    const int n0 = blockIdx.x * TILE_N;
    const int m0 = blockIdx.y * TILE_M;

    const int8_t* xa = g_x8 + (size_t)m0 * K_TOTAL;
    const int8_t* wb = g_w8 + (size_t)n0 * K_TOTAL;

    // ---- cp.async coordinates: 8 granules/thread ----
    // j<4 -> A rows 0..127 (swizzled); j>=4 -> B rows 0..127
    // (rows <80 swizzled for mma, rows >=80 LINEAR for dp4a)
    uint32_t dst_off[8], src_off[8];
    #pragma unroll
    for (int j = 0; j < 8; j++) {
        const int idx = (tid + j * 256) & 1023;
        const int row = idx >> 3, g = idx & 7;
        uint32_t sw;
        if (j < 4) {
            sw = (uint32_t)(row * 128 + ((g ^ (row & 7)) << 4));
        } else if (row < N_MMA) {
            sw = (uint32_t)A_BYTES + (uint32_t)(row * 128 + ((g ^ (row & 7)) << 4));
        } else {
            sw = (uint32_t)A_BYTES + (uint32_t)(row * 128 + g * 16);   // linear
        }
        dst_off[j] = sw;
        src_off[j] = (uint32_t)(row * K_TOTAL + g * 16);
    }

    // ---- per-role addressing ----
    const int li = lane >> 2;      // mma swizzle key
    const int lq = lane & 3;
    const int mg = lane >> 3;      // dp4a m-group (0..3)
    const int ng = lane & 7;       // dp4a n-group (0..7)

    // single dynamic bases; fragments addressed with immediates off them
    uint32_t a_base, b_base;
    if (is_mma) {
        a_base = (uint32_t)((wid * 32 + li) * 128);            // + t*2048 + h*1024
        b_base = (uint32_t)(A_BYTES + li * 128);               // + nt*1024
    } else {
        a_base = (uint32_t)(((wid - 4) * 32 + mg * 8) * 128);  // + i*128 (+XOR)
        b_base = (uint32_t)(B_DP_OFF + ng * 6 * 128);          // + j*128 + v*8
    }

    int acc[80];
    #pragma unroll
    for (int i = 0; i < 80; i++) acc[i] = 0;

    // ---- prologue: stages 0..1 ----
    #pragma unroll
    for (int s = 0; s < STAGES - 1; s++) {
        const uint32_t sbuf = smem_base + s * STAGE_BYTES;
        const uint32_t koff = (uint32_t)s * TILE_K;
        #pragma unroll
        for (int j = 0; j < 8; j++) {
            const int8_t* base = (j < 4) ? xa : wb;
            cp_async16(sbuf + dst_off[j], base + src_off[j] + koff);
        }
        asm volatile("cp.async.commit_group;" ::: "memory");
    }

    // ---- main loop ----
    for (int it = 0; it < K_ITERS; it++) {
        asm volatile("cp.async.wait_group %0;" :: "n"(STAGES - 2) : "memory");
        __syncthreads();

        if (it + STAGES - 1 < K_ITERS) {
            const int s = it + STAGES - 1;
            const uint32_t sbuf = smem_base + (s % STAGES) * STAGE_BYTES;
            const uint32_t koff = (uint32_t)s * TILE_K;
            #pragma unroll
            for (int j = 0; j < 8; j++) {
                const int8_t* base = (j < 4) ? xa : wb;
                cp_async16(sbuf + dst_off[j], base + src_off[j] + koff);
            }
        }
        asm volatile("cp.async.commit_group;" ::: "memory");

        const uint32_t sbuf = smem_base + (it % STAGES) * STAGE_BYTES;

        if (is_mma) {
            // ===== tensor side: cols 0-79 (10 n-tiles) =====
            const uint32_t ab = sbuf + a_base;
            const uint32_t bb = sbuf + b_base;
            #pragma unroll
            for (int kk = 0; kk < 4; kk++) {
                const uint32_t off_lo = (uint32_t)(((((kk << 1) | 0) ^ li) << 4) + 4 * lq);
                const uint32_t off_hi = (uint32_t)(((((kk << 1) | 1) ^ li) << 4) + 4 * lq);
                const uint32_t alo = ab + off_lo, ahi = ab + off_hi;
                const uint32_t blo = bb + off_lo, bhi = bb + off_hi;

                uint32_t afr[2][4];
                #pragma unroll
                for (int t = 0; t < 2; t++) {
                    afr[t][0] = lds32(alo + t * 2048);
                    afr[t][1] = lds32(alo + t * 2048 + 1024);
                    afr[t][2] = lds32(ahi + t * 2048);
                    afr[t][3] = lds32(ahi + t * 2048 + 1024);
                }
                uint32_t bfr[NT_MMA][2];
                #pragma unroll
                for (int nt = 0; nt < NT_MMA; nt++) {
                    bfr[nt][0] = lds32(blo + nt * 1024);
                    bfr[nt][1] = lds32(bhi + nt * 1024);
                }
                #pragma unroll
                for (int t = 0; t < 2; t++)
                    #pragma unroll
                    for (int nt = 0; nt < NT_MMA; nt++)
                        mma_s8(&acc[(t * NT_MMA + nt) * 4], afr[t], bfr[nt]);
            }
        } else {
            // ===== dp4a side: cols 80-127, 8m x 6n per thread =====
            // a: swizzled region, per-lane k-pair rotation (conflict-free)
            // b: LINEAR region, addr = b_base + v*8 + imm(j*128)
            const uint32_t ab = sbuf + a_base;
            const uint32_t bb = sbuf + b_base;
            #pragma unroll 4
            for (int wp = 0; wp < 16; wp++) {
                const int p = (wp + lane) & 15;
                const uint32_t gi = (uint32_t)(p >> 1);
                const uint32_t low = (uint32_t)(p & 1) * 8;
                const uint32_t bv = bb + (uint32_t)p * 8;
                uint32_t a[8][2], b[6][2];
                #pragma unroll
                for (int i = 0; i < 8; i++)
                    lds64(a[i][0], a[i][1], ab + i * 128 + (((gi ^ (uint32_t)i) << 4) | low));
                #pragma unroll
                for (int j = 0; j < 6; j++)
                    lds64(b[j][0], b[j][1], bv + j * 128);
                #pragma unroll
                for (int i = 0; i < 8; i++)
                    #pragma unroll
                    for (int j = 0; j < 6; j++) {
                        acc[i * 6 + j] = dp4a_s(a[i][0], b[j][0], acc[i * 6 + j]);
                        acc[i * 6 + j] = dp4a_s(a[i][1], b[j][1], acc[i * 6 + j]);
                    }
            }
        }
    }

    // ---- epilogue ----
    if (is_mma) {
        const int m_base = m0 + wid * 32 + li;
        const int n_base = n0 + 2 * lq;
        #pragma unroll
        for (int nt = 0; nt < NT_MMA; nt++) {
            const int col = n_base + nt * 8;
            const int bv0 = g_bias[col];
            const int bv1 = g_bias[col + 1];
            #pragma unroll
            for (int t = 0; t < 2; t++) {
                const int r0 = m_base + t * 16;
                const int* c = &acc[(t * NT_MMA + nt) * 4];
                float2 v0, v1;
                v0.x = (float)(c[0] + bv0);
                v0.y = (float)(c[1] + bv1);
                v1.x = (float)(c[2] + bv0);
                v1.y = (float)(c[3] + bv1);
                *reinterpret_cast<float2*>(out + (size_t)r0 * N_TOTAL + col) = v0;
                *reinterpret_cast<float2*>(out + (size_t)(r0 + 8) * N_TOTAL + col) = v1;
            }
        }
    } else {
        const int m_base = m0 + (wid - 4) * 32 + mg * 8;
        const int n_base = n0 + N_MMA + ng * 6;
        int bv[6];
        #pragma unroll
        for (int j = 0; j < 6; j++) bv[j] = g_bias[n_base + j];
        #pragma unroll
        for (int i = 0; i < 8; i++) {
            float* op = out + (size_t)(m_base + i) * N_TOTAL + n_base;
            #pragma unroll
            for (int j = 0; j < 6; j += 2) {
                float2 v;
                v.x = (float)(acc[i * 6 + j] + bv[j]);
                v.y = (float)(acc[i * 6 + j + 1] + bv[j + 1]);
                *reinterpret_cast<float2*>(op + j) = v;
            }
        }
    }
}

// ---------------------------------------------------------------------------
// Launch
// ---------------------------------------------------------------------------
extern "C" void kernel_launch(void* const* d_in, const int* in_sizes, int n_in,
                              void* d_out, int out_size) {
    int ix = 0, iw = 0, ib = 0;
    for (int i = 1; i < n_in && i < 3; i++) {
        if (in_sizes[i] > in_sizes[ix]) ix = i;
        if (in_sizes[i] < in_sizes[ib]) ib = i;
    }
    for (int i = 0; i < 3; i++) if (i != ix && i != ib) iw = i;

    const uint8_t* x    = (const uint8_t*)d_in[ix];
    const uint8_t* w    = (const uint8_t*)d_in[iw];
    const uint8_t* bias = (const uint8_t*)d_in[ib];
    float*         out  = (float*)d_out;

    const int x_words = (M_TOTAL * K_TOTAL) / 4;
    const int w_words = (N_TOTAL * K_TOTAL) / 4;
    pack_s8_kernel<<<x_words / 256, 256>>>(x, x_words, 0);
    pack_s8_kernel<<<w_words / 256, 256>>>(w, w_words, 1);
    pack_bias_kernel<<<N_TOTAL / 256, 256>>>(bias);

    cudaFuncSetAttribute(w8a8_hybrid_kernel,
                         cudaFuncAttributeMaxDynamicSharedMemorySize, SMEM_BYTES);
    dim3 grid(N_TOTAL / TILE_N, M_TOTAL / TILE_M);   // (32, 64)
    w8a8_hybrid_kernel<<<grid, THREADS, SMEM_BYTES>>>(out);
}

// round 13
// speedup vs baseline: 1.0007x; 1.0007x over previous
#include <cuda_runtime.h>
#include <cstdint>
#include <cmath>

// ============================================================================
// W8A8B32O32 Linear — hybrid 80/48, 384-thread / 8-feeder-warp build.
// out[8192,4096](f32) = X[8192,4096](s8) @ W[4096,4096](s8)^T + bias(s32)
//
// R12 diagnosis: tensor pinned at 79% because only 2 mma warps/SMSP feed it
// (128-reg kernel = register-file-full at 16 warps/SM). This build keeps the
// 80/48 split but spreads the mma work over 8 warps (32x40 tile, 40 accs,
// ~75 regs) + 4 dp4a warps -> 2 CTAs x 12 warps = 24 warps/SM, 4 tensor
// feeders per SMSP. 3-stage cp.async, 96KB smem, 2 CTAs/SM.
// ============================================================================

#define M_TOTAL   8192
#define N_TOTAL   4096
#define K_TOTAL   4096

#define THREADS   384

#define TILE_M    128
#define TILE_N    128
#define TILE_K    128
#define K_ITERS   (K_TOTAL / TILE_K)   // 32
#define STAGES    3

#define N_MMA     80                   // cols 0-79: 8 mma warps (4m x 2n, 32x40)
#define NT_WARP   5                    // n-tiles per mma warp
#define N_DP      48                   // cols 80-127: 4 dp4a warps

#define A_BYTES      (TILE_M * TILE_K)            // 16384
#define B_BYTES      (TILE_N * TILE_K)            // 16384
#define B_DP_OFF     (A_BYTES + N_MMA * 128)      // dp4a-B region (linear)
#define STAGE_BYTES  (A_BYTES + B_BYTES)          // 32768
#define SMEM_BYTES   (STAGES * STAGE_BYTES)       // 98304 -> 2 CTAs/SM

// __device__ scratch (allocation-free rule)
__device__ int8_t g_x8[(size_t)M_TOTAL * K_TOTAL];
__device__ int8_t g_w8[(size_t)N_TOTAL * K_TOTAL];
__device__ int    g_bias[N_TOTAL];

// ---------------------------------------------------------------------------
// Stage 1: encoding detection + pack (proven R7-R12)
// ---------------------------------------------------------------------------
__device__ __forceinline__ int bf16_half_ok(uint32_t h, float rng) {
    if (h == 0) return -1;
    float f = __uint_as_float(h << 16);
    return (f == truncf(f) && fabsf(f) <= rng && f != 0.0f) ? 1 : 0;
}

__device__ __forceinline__ int detect_mode(const uint32_t* in32, int tid, int* cnt, float rng) {
    if (tid < 3) cnt[tid] = 0;
    __syncthreads();
    if (tid < 64) {
        const uint32_t w = in32[tid];
        const int   wi = (int)w;
        const float wf = __uint_as_float(w);
        if (wi != 0 && wi > (int)-rng && wi < (int)rng) atomicAdd(&cnt[0], 1);
        if (wf != 0.0f && wf == truncf(wf) && fabsf(wf) <= rng) atomicAdd(&cnt[1], 1);
        const int lo = bf16_half_ok(w & 0xFFFFu, rng);
        const int hi = bf16_half_ok(w >> 16, rng);
        if (lo != 0 && hi != 0 && (lo == 1 || hi == 1)) atomicAdd(&cnt[2], 1);
    }
    __syncthreads();
    if (cnt[0] >= 48) return 1;
    if (cnt[1] >= 48) return 2;
    if (cnt[2] >= 48) return 3;
    return 0;
}

__global__ void pack_s8_kernel(const uint8_t* __restrict__ in, int n_words, int which) {
    __shared__ int cnt[3];
    const int tid = threadIdx.x;
    const uint32_t* in32 = (const uint32_t*)in;
    const int mode = detect_mode(in32, tid, cnt, 128.0f);

    uint8_t* out = which ? (uint8_t*)g_w8 : (uint8_t*)g_x8;
    const int o = blockIdx.x * blockDim.x + tid;
    if (o >= n_words) return;

    uint32_t r;
    if (mode == 0) {
        r = in32[o];
    } else if (mode == 1) {
        const int4 v = ((const int4*)in)[o];
        r = (uint32_t)(v.x & 0xFF) | ((uint32_t)(v.y & 0xFF) << 8) |
            ((uint32_t)(v.z & 0xFF) << 16) | ((uint32_t)(v.w & 0xFF) << 24);
    } else if (mode == 2) {
        const float4 v = ((const float4*)in)[o];
        const int e0 = (int)v.x, e1 = (int)v.y, e2 = (int)v.z, e3 = (int)v.w;
        r = (uint32_t)(e0 & 0xFF) | ((uint32_t)(e1 & 0xFF) << 8) |
            ((uint32_t)(e2 & 0xFF) << 16) | ((uint32_t)(e3 & 0xFF) << 24);
    } else {
        const uint32_t w0 = in32[2 * o], w1 = in32[2 * o + 1];
        const int e0 = (int)__uint_as_float((w0 & 0xFFFFu) << 16);
        const int e1 = (int)__uint_as_float((w0 >> 16) << 16);
        const int e2 = (int)__uint_as_float((w1 & 0xFFFFu) << 16);
        const int e3 = (int)__uint_as_float((w1 >> 16) << 16);
        r = (uint32_t)(e0 & 0xFF) | ((uint32_t)(e1 & 0xFF) << 8) |
            ((uint32_t)(e2 & 0xFF) << 16) | ((uint32_t)(e3 & 0xFF) << 24);
    }
    ((uint32_t*)out)[o] = r;
}

__global__ void pack_bias_kernel(const uint8_t* __restrict__ in) {
    __shared__ int cnt[3];
    const int tid = threadIdx.x;
    const uint32_t* in32 = (const uint32_t*)in;
    const int mode = detect_mode(in32, tid, cnt, 100000.0f);

    const int o = blockIdx.x * blockDim.x + tid;
    if (o >= N_TOTAL) return;

    int v;
    if (mode == 2)      v = (int)__uint_as_float(in32[o]);
    else if (mode == 3) {
        const uint32_t h = (in32[o >> 1] >> ((o & 1) * 16)) & 0xFFFFu;
        v = (int)__uint_as_float(h << 16);
    } else              v = (int)in32[o];
    g_bias[o] = v;
}

// ---------------------------------------------------------------------------
// helpers
// ---------------------------------------------------------------------------
__device__ __forceinline__ uint32_t smem_u32(const void* p) {
    uint32_t a;
    asm("{ .reg .u64 t; cvta.to.shared.u64 t, %1; cvt.u32.u64 %0, t; }" : "=r"(a) : "l"(p));
    return a;
}
__device__ __forceinline__ void cp_async16(uint32_t dst, const void* src) {
    asm volatile("cp.async.cg.shared.global [%0], [%1], 16;" :: "r"(dst), "l"(src) : "memory");
}
__device__ __forceinline__ uint32_t lds32(uint32_t addr) {
    uint32_t v;
    asm volatile("ld.shared.b32 %0, [%1];" : "=r"(v) : "r"(addr));
    return v;
}
__device__ __forceinline__ void lds64(uint32_t& v0, uint32_t& v1, uint32_t addr) {
    asm volatile("ld.shared.v2.u32 {%0,%1}, [%2];" : "=r"(v0), "=r"(v1) : "r"(addr));
}
__device__ __forceinline__ void mma_s8(int* c, const uint32_t* a, const uint32_t* b) {
    asm volatile(
        "mma.sync.aligned.m16n8k32.row.col.s32.s8.s8.s32 "
        "{%0,%1,%2,%3}, {%4,%5,%6,%7}, {%8,%9}, {%0,%1,%2,%3};"
        : "+r"(c[0]), "+r"(c[1]), "+r"(c[2]), "+r"(c[3])
        : "r"(a[0]), "r"(a[1]), "r"(a[2]), "r"(a[3]), "r"(b[0]), "r"(b[1]));
}
__device__ __forceinline__ int dp4a_s(uint32_t a, uint32_t b, int c) {
    int r;
    asm("dp4a.s32.s32 %0, %1, %2, %3;" : "=r"(r) : "r"(a), "r"(b), "r"(c));
    return r;
}

// ---------------------------------------------------------------------------
// Stage 2: hybrid GEMM, 80/48 split, 384 threads, 2 CTAs/SM
// ---------------------------------------------------------------------------
__global__ void __launch_bounds__(THREADS, 2)
w8a8_hybrid_kernel(float* __restrict__ out) {
    extern __shared__ char smem[];
    const uint32_t smem_base = smem_u32(smem);
    const int tid = threadIdx.x;
    const int lane = tid & 31;
    const int wid = tid >> 5;
    const bool is_mma = (wid < 8);

    const int n0 = blockIdx.x * TILE_N;
    const int m0 = blockIdx.y * TILE_M;

    const int8_t* xa = g_x8 + (size_t)m0 * K_TOTAL;
    const int8_t* wb = g_w8 + (size_t)n0 * K_TOTAL;

    // ---- cp.async coordinates: 2048 granules over 384 threads (6/thread, guarded) ----
    uint32_t dst_off[6], src_off[6];
    bool     g_ok[6];
    #pragma unroll
    for (int j = 0; j < 6; j++) {
        const int gidx = tid + j * THREADS;
        g_ok[j] = (gidx < 2048);
        const int idx = gidx & 1023;
        const int row = idx >> 3, g = idx & 7;
        uint32_t sw;
        if (gidx < 1024) {
            sw = (uint32_t)(row * 128 + ((g ^ (row & 7)) << 4));
        } else if (row < N_MMA) {
            sw = (uint32_t)A_BYTES + (uint32_t)(row * 128 + ((g ^ (row & 7)) << 4));
        } else {
            sw = (uint32_t)A_BYTES + (uint32_t)(row * 128 + g * 16);   // linear
        }
        dst_off[j] = sw;
        src_off[j] = (uint32_t)(row * K_TOTAL + g * 16);
    }

    // ---- per-role addressing ----
    const int li = lane >> 2;      // mma swizzle key
    const int lq = lane & 3;
    const int mg = lane >> 3;      // dp4a m-group (0..3)
    const int ng = lane & 7;       // dp4a n-group (0..7)

    uint32_t a_base, b_base;
    if (is_mma) {
        const int warp_m = wid & 3, warp_n = wid >> 2;      // 4m x 2n warp grid
        a_base = (uint32_t)((warp_m * 32 + li) * 128);              // + t*2048 + h*1024
        b_base = (uint32_t)(A_BYTES + (warp_n * 40 + li) * 128);    // + nt*1024
    } else {
        const int dw = wid - 8;                              // 0..3
        a_base = (uint32_t)((dw * 32 + mg * 8) * 128);       // + i*128 (+XOR)
        b_base = (uint32_t)(B_DP_OFF + ng * 6 * 128);        // + j*128 + p*8
    }

    int acc[48];
    #pragma unroll
    for (int i = 0; i < 48; i++) acc[i] = 0;

    // ---- prologue: stages 0..1 ----
    #pragma unroll
    for (int s = 0; s < STAGES - 1; s++) {
        const uint32_t sbuf = smem_base + s * STAGE_BYTES;
        const uint32_t koff = (uint32_t)s * TILE_K;
        #pragma unroll
        for (int j = 0; j < 6; j++) {
            if (g_ok[j]) {
                const int8_t* base = (tid + j * THREADS < 1024) ? xa : wb;
                cp_async16(sbuf + dst_off[j], base + src_off[j] + koff);
            }
        }
        asm volatile("cp.async.commit_group;" ::: "memory");
    }

    // ---- main loop ----
    for (int it = 0; it < K_ITERS; it++) {
        asm volatile("cp.async.wait_group %0;" :: "n"(STAGES - 2) : "memory");
        __syncthreads();

        if (it + STAGES - 1 < K_ITERS) {
            const int s = it + STAGES - 1;
            const uint32_t sbuf = smem_base + (s % STAGES) * STAGE_BYTES;
            const uint32_t koff = (uint32_t)s * TILE_K;
            #pragma unroll
            for (int j = 0; j < 6; j++) {
                if (g_ok[j]) {
                    const int8_t* base = (tid + j * THREADS < 1024) ? xa : wb;
                    cp_async16(sbuf + dst_off[j], base + src_off[j] + koff);
                }
            }
        }
        asm volatile("cp.async.commit_group;" ::: "memory");

        const uint32_t sbuf = smem_base + (it % STAGES) * STAGE_BYTES;

        if (is_mma) {
            // ===== tensor side: warp tile 32m x 40n (5 n-tiles) =====
            const uint32_t ab = sbuf + a_base;
            const uint32_t bb = sbuf + b_base;
            #pragma unroll
            for (int kk = 0; kk < 4; kk++) {
                const uint32_t off_lo = (uint32_t)(((((kk << 1) | 0) ^ li) << 4) + 4 * lq);
                const uint32_t off_hi = (uint32_t)(((((kk << 1) | 1) ^ li) << 4) + 4 * lq);
                const uint32_t alo = ab + off_lo, ahi = ab + off_hi;
                const uint32_t blo = bb + off_lo, bhi = bb + off_hi;

                uint32_t afr[2][4];
                #pragma unroll
                for (int t = 0; t < 2; t++) {
                    afr[t][0] = lds32(alo + t * 2048);
                    afr[t][1] = lds32(alo + t * 2048 + 1024);
                    afr[t][2] = lds32(ahi + t * 2048);
                    afr[t][3] = lds32(ahi + t * 2048 + 1024);
                }
                uint32_t bfr[NT_WARP][2];
                #pragma unroll
                for (int nt = 0; nt < NT_WARP; nt++) {
                    bfr[nt][0] = lds32(blo + nt * 1024);
                    bfr[nt][1] = lds32(bhi + nt * 1024);
                }
                #pragma unroll
                for (int t = 0; t < 2; t++)
                    #pragma unroll
                    for (int nt = 0; nt < NT_WARP; nt++)
                        mma_s8(&acc[(t * NT_WARP + nt) * 4], afr[t], bfr[nt]);
            }
        } else {
            // ===== dp4a side: cols 80-127, 8m x 6n per thread =====
            // a: swizzled region, per-lane pair rotation; b: linear region.
            // b loaded per-j (2 live regs) to cap register pressure.
            const uint32_t ab = sbuf + a_base;
            const uint32_t bb = sbuf + b_base;
            #pragma unroll 4
            for (int wp = 0; wp < 16; wp++) {
                const int p = (wp + lane) & 15;
                const uint32_t gi = (uint32_t)(p >> 1);
                const uint32_t low = (uint32_t)(p & 1) * 8;
                const uint32_t bv = bb + (uint32_t)p * 8;
                uint32_t a[8][2];
                #pragma unroll
                for (int i = 0; i < 8; i++)
                    lds64(a[i][0], a[i][1], ab + i * 128 + (((gi ^ (uint32_t)i) << 4) | low));
                #pragma unroll
                for (int j = 0; j < 6; j++) {
                    uint32_t b0, b1;
                    lds64(b0, b1, bv + j * 128);
                    #pragma unroll
                    for (int i = 0; i < 8; i++) {
                        acc[i * 6 + j] = dp4a_s(a[i][0], b0, acc[i * 6 + j]);
                        acc[i * 6 + j] = dp4a_s(a[i][1], b1, acc[i * 6 + j]);
                    }
                }
            }
        }
    }

    // ---- epilogue ----
    if (is_mma) {
        const int warp_m = wid & 3, warp_n = wid >> 2;
        const int m_base = m0 + warp_m * 32 + li;
        const int n_base = n0 + warp_n * 40 + 2 * lq;
        #pragma unroll
        for (int nt = 0; nt < NT_WARP; nt++) {
            const int col = n_base + nt * 8;
            const int bv0 = g_bias[col];
            const int bv1 = g_bias[col + 1];
            #pragma unroll
            for (int t = 0; t < 2; t++) {
                const int r0 = m_base + t * 16;
                const int* c = &acc[(t * NT_WARP + nt) * 4];
                float2 v0, v1;
                v0.x = (float)(c[0] + bv0);
                v0.y = (float)(c[1] + bv1);
                v1.x = (float)(c[2] + bv0);
                v1.y = (float)(c[3] + bv1);
                *reinterpret_cast<float2*>(out + (size_t)r0 * N_TOTAL + col) = v0;
                *reinterpret_cast<float2*>(out + (size_t)(r0 + 8) * N_TOTAL + col) = v1;
            }
        }
    } else {
        const int dw = wid - 8;
        const int m_base = m0 + dw * 32 + mg * 8;
        const int n_base = n0 + N_MMA + ng * 6;
        int bv[6];
        #pragma unroll
        for (int j = 0; j < 6; j++) bv[j] = g_bias[n_base + j];
        #pragma unroll
        for (int i = 0; i < 8; i++) {
            float* op = out + (size_t)(m_base + i) * N_TOTAL + n_base;
            #pragma unroll
            for (int j = 0; j < 6; j += 2) {
                float2 v;
                v.x = (float)(acc[i * 6 + j] + bv[j]);
                v.y = (float)(acc[i * 6 + j + 1] + bv[j + 1]);
                *reinterpret_cast<float2*>(op + j) = v;
            }
        }
    }
}

// ---------------------------------------------------------------------------
// Launch
// ---------------------------------------------------------------------------
extern "C" void kernel_launch(void* const* d_in, const int* in_sizes, int n_in,
                              void* d_out, int out_size) {
    int ix = 0, iw = 0, ib = 0;
    for (int i = 1; i < n_in && i < 3; i++) {
        if (in_sizes[i] > in_sizes[ix]) ix = i;
        if (in_sizes[i] < in_sizes[ib]) ib = i;
    }
    for (int i = 0; i < 3; i++) if (i != ix && i != ib) iw = i;

    const uint8_t* x    = (const uint8_t*)d_in[ix];
    const uint8_t* w    = (const uint8_t*)d_in[iw];
    const uint8_t* bias = (const uint8_t*)d_in[ib];
    float*         out  = (float*)d_out;

    const int x_words = (M_TOTAL * K_TOTAL) / 4;
    const int w_words = (N_TOTAL * K_TOTAL) / 4;
    pack_s8_kernel<<<x_words / 256, 256>>>(x, x_words, 0);
    pack_s8_kernel<<<w_words / 256, 256>>>(w, w_words, 1);
    pack_bias_kernel<<<N_TOTAL / 256, 256>>>(bias);

    cudaFuncSetAttribute(w8a8_hybrid_kernel,
                         cudaFuncAttributeMaxDynamicSharedMemorySize, SMEM_BYTES);
    dim3 grid(N_TOTAL / TILE_N, M_TOTAL / TILE_M);   // (32, 64)
    w8a8_hybrid_kernel<<<grid, THREADS, SMEM_BYTES>>>(out);
}